// round 15
// baseline (speedup 1.0000x reference)
#include <cuda_runtime.h>
#include <cuda_fp16.h>
#include <math.h>

#define N_NODES 100000
#define N_HID   256
#define N_EDGES 3200000

// bit-reinterpret helpers
static __device__ __forceinline__ unsigned h2_to_u32(__half2 h) {
    union { __half2 h; unsigned u; } c; c.h = h; return c.u;
}
static __device__ __forceinline__ __half2 u32_to_h2(unsigned u) {
    union { unsigned u; __half2 h; } c; c.u = u; return c.h;
}

// ---- scratch in device globals (no allocation allowed) ----
__device__ int    g_out_deg[N_NODES];
__device__ float  g_hun[N_NODES];                       // unscaled dot
__device__ __half g_h1h[N_NODES];                       // scaled h, fp16 gather table
__device__ __align__(8) float2 g_aggcnt[N_NODES];       // {agg_sum, in_deg_count}
__device__ __align__(16) __half g_xh[N_NODES * N_HID];  // x = input + pe, fp16
__device__ float  g_W1[N_HID];                          // W[:,1]
__device__ float  g_pe_s[N_HID];                        // pe_coff * pe(t+1)
__device__ float  g_pe_dot;
__device__ float  g_b1;

// K0: zero scratch + compute PE row, W1, pe_dot, b1.
__global__ void k_init(const float* __restrict__ W,
                       const float* __restrict__ b,
                       const float* __restrict__ pe_coff,
                       const int*   __restrict__ t_ptr) {
    int i = blockIdx.x * blockDim.x + threadIdx.x;
    if (i < N_NODES) {
        g_out_deg[i] = 0;
        g_aggcnt[i]  = make_float2(0.0f, 0.0f);
    }
    if (blockIdx.x == 0) {
        int c = threadIdx.x;               // 256 threads == N_HID
        float w1 = W[c * 2 + 1];
        g_W1[c] = w1;
        int t = *t_ptr;
        float pos  = (float)(t + 1);
        float coff = pe_coff[0];
        int even = c & ~1;
        float div = expf((float)even * (-logf(10000.0f) / (float)N_HID));
        float pe  = (c & 1) ? cosf(pos * div) : sinf(pos * div);
        float pes = coff * pe;
        g_pe_s[c] = pes;
        __shared__ float sred[256];
        sred[c] = pes * w1;
        __syncthreads();
        for (int s = 128; s > 0; s >>= 1) {
            if (c < s) sred[c] += sred[c + s];
            __syncthreads();
        }
        if (c == 0) {
            g_pe_dot = sred[0];
            g_b1 = b[1];
        }
    }
}

// K1 fused: interleaved block roles (1 edge block per 4 node blocks).
#define FUSED_GRID 15625
__global__ void k_fused(const float* __restrict__ input,
                        const int*   __restrict__ src) {
    int b = blockIdx.x;
    if (b % 5 == 0) {
        // ---- edge role: out-degree atomics ----
        int eb = b / 5;
        int i = eb * 256 + threadIdx.x;
        int4 s = make_int4(0, 0, 0, 0);
        bool act = (i < N_EDGES / 4);
        if (act) s = __ldcs(&((const int4*)src)[i]);   // streaming
        cudaGridDependencySynchronize();               // k_init zeroed counters
        if (act) {
            atomicAdd(&g_out_deg[s.x], 1);
            atomicAdd(&g_out_deg[s.y], 1);
            atomicAdd(&g_out_deg[s.z], 1);
            atomicAdd(&g_out_deg[s.w], 1);
        }
    } else {
        // ---- node role: dot(input[r], W1) + write x_h[r] fp16 ----
        int nb = b - (b / 5 + 1);            // 0..12499
        int warp_in_block = threadIdx.x >> 5;
        int lane = threadIdx.x & 31;
        int row = nb * 8 + warp_in_block;
        float4 v0 = make_float4(0, 0, 0, 0), v1 = v0;
        bool act = (row < N_NODES);
        if (act) {
            const float4* rowp = (const float4*)(input + (size_t)row * N_HID);
            v0 = __ldcs(&rowp[2 * lane]);       // streaming: not needed later
            v1 = __ldcs(&rowp[2 * lane + 1]);
        }
        cudaGridDependencySynchronize();               // g_W1 / g_pe_s from k_init
        if (act) {
            const float4* w4 = (const float4*)g_W1;
            const float4* p4 = (const float4*)g_pe_s;
            float4 w0 = w4[2 * lane];
            float4 w1 = w4[2 * lane + 1];
            float acc = v0.x * w0.x + v0.y * w0.y + v0.z * w0.z + v0.w * w0.w
                      + v1.x * w1.x + v1.y * w1.y + v1.z * w1.z + v1.w * w1.w;
#pragma unroll
            for (int o = 16; o > 0; o >>= 1)
                acc += __shfl_xor_sync(0xffffffffu, acc, o);
            if (lane == 0) g_hun[row] = acc;
            float4 p0 = p4[2 * lane];
            float4 p1 = p4[2 * lane + 1];
            uint4 pk;
            pk.x = h2_to_u32(__floats2half2_rn(v0.x + p0.x, v0.y + p0.y));
            pk.y = h2_to_u32(__floats2half2_rn(v0.z + p0.z, v0.w + p0.w));
            pk.z = h2_to_u32(__floats2half2_rn(v1.x + p1.x, v1.y + p1.y));
            pk.w = h2_to_u32(__floats2half2_rn(v1.z + p1.z, v1.w + p1.w));
            ((uint4*)g_xh)[(size_t)row * 32 + lane] = pk;   // default: L2-resident
        }
    }
}

// K2: scale by out-degree norm, store fp16 gather table (tiny)
__global__ void k_scale() {
    int i = blockIdx.x * blockDim.x + threadIdx.x;
    cudaGridDependencySynchronize();
    if (i >= N_NODES) return;
    float od = (float)max(g_out_deg[i], 1);
    g_h1h[i] = __float2half((g_hun[i] + g_pe_dot) * rsqrtf(od));
}

// K3: persistent edge aggregation. fp16 h table in SMEM (LDS gather),
//     one fp32 v2 RED per edge: {h,1} -> {agg,cnt}.
__global__ void __launch_bounds__(1024, 1)
k_agg(const int* __restrict__ src, const int* __restrict__ dst) {
    extern __shared__ __half sh[];   // N_NODES halves = 200000 bytes
    int tid = blockIdx.x * blockDim.x + threadIdx.x;
    int nth = gridDim.x * blockDim.x;
    cudaGridDependencySynchronize();                   // h table ready (k_scale)
    for (int j = threadIdx.x; j < N_NODES / 8; j += blockDim.x)
        ((uint4*)sh)[j] = ((const uint4*)g_h1h)[j];
    __syncthreads();
    const float one = 1.0f;
    const int n4 = N_EDGES / 4;
    for (int i = tid; i < n4; i += nth) {
        int4 s = __ldcs(&((const int4*)src)[i]);
        int4 d = __ldcs(&((const int4*)dst)[i]);
        float h0 = __half2float(sh[s.x]);
        float h1 = __half2float(sh[s.y]);
        float h2 = __half2float(sh[s.z]);
        float h3 = __half2float(sh[s.w]);
#define REDV2(p, h) asm volatile("red.global.add.v2.f32 [%0], {%1, %2};" :: "l"(p), "f"(h), "f"(one) : "memory")
        REDV2(&g_aggcnt[d.x], h0);
        REDV2(&g_aggcnt[d.y], h1);
        REDV2(&g_aggcnt[d.z], h2);
        REDV2(&g_aggcnt[d.w], h3);
#undef REDV2
    }
}

// K4: out[r][c] = x_h[r][c] * gate(r).  16 floats/thread.
//     PROLOGUE loads x_h BEFORE the PDL sync (x_h final since k_fused,
//     two launches back) — overlaps the 51MB read with k_agg's atomic tail.
__global__ void __launch_bounds__(256)
k_out(float* __restrict__ out) {
    int idx = blockIdx.x * blockDim.x + threadIdx.x;   // 0 .. 1.6M-1
    const int total16 = N_NODES * (N_HID / 16);        // 1.6M
    bool act = (idx < total16);
    uint4 pka = make_uint4(0, 0, 0, 0), pkb = pka;
    if (act) {
        pka = __ldg(&((const uint4*)g_xh)[2 * idx]);
        pkb = __ldg(&((const uint4*)g_xh)[2 * idx + 1]);
    }
    cudaGridDependencySynchronize();                   // aggcnt final
    if (!act) return;
    int row = idx >> 4;                                // N_HID/16 == 16
    float2 ac = g_aggcnt[row];
    float z = ac.x * rsqrtf(fmaxf(ac.y, 1.0f)) + g_b1;
    z = fmaxf(z, 0.0f);
    float gate = 1.0f / (1.0f + expf(-z));
    float* p = out + (size_t)idx * 16;
#define GATE8(pk, ptr)                                                         \
    {                                                                          \
        float2 f0 = __half22float2(u32_to_h2((pk).x));                         \
        float2 f1 = __half22float2(u32_to_h2((pk).y));                         \
        float2 f2 = __half22float2(u32_to_h2((pk).z));                         \
        float2 f3 = __half22float2(u32_to_h2((pk).w));                         \
        asm volatile("st.global.cs.v8.f32 [%0], {%1,%2,%3,%4,%5,%6,%7,%8};"    \
                     :: "l"(ptr),                                              \
                        "f"(f0.x * gate), "f"(f0.y * gate),                    \
                        "f"(f1.x * gate), "f"(f1.y * gate),                    \
                        "f"(f2.x * gate), "f"(f2.y * gate),                    \
                        "f"(f3.x * gate), "f"(f3.y * gate) : "memory");        \
    }
    GATE8(pka, p);
    GATE8(pkb, p + 8);
#undef GATE8
}

template <typename K, typename... Args>
static inline void launch_pdl(K kern, int grid, int block, size_t smem, Args... args) {
    cudaLaunchConfig_t cfg = {};
    cfg.gridDim = dim3(grid, 1, 1);
    cfg.blockDim = dim3(block, 1, 1);
    cfg.dynamicSmemBytes = smem;
    cfg.stream = 0;
    cudaLaunchAttribute attr[1];
    attr[0].id = cudaLaunchAttributeProgrammaticStreamSerialization;
    attr[0].val.programmaticStreamSerializationAllowed = 1;
    cfg.attrs = attr;
    cfg.numAttrs = 1;
    cudaLaunchKernelEx(&cfg, kern, args...);
}

extern "C" void kernel_launch(void* const* d_in, const int* in_sizes, int n_in,
                              void* d_out, int out_size) {
    const float* input   = (const float*)d_in[0];
    const float* W       = (const float*)d_in[1];
    const float* b       = (const float*)d_in[2];
    const float* pe_coff = (const float*)d_in[3];
    const int*   src     = (const int*)d_in[4];
    const int*   dst     = (const int*)d_in[5];
    const int*   t_ptr   = (const int*)d_in[6];
    float* out = (float*)d_out;

    const size_t AGG_SMEM = (size_t)N_NODES * sizeof(__half);   // 200000 B
    cudaFuncSetAttribute(k_agg, cudaFuncAttributeMaxDynamicSharedMemorySize,
                         (int)AGG_SMEM);
    int n_sm = 148;
    cudaDeviceGetAttribute(&n_sm, cudaDevAttrMultiProcessorCount, 0);
    if (n_sm <= 0) n_sm = 148;

    k_init<<<1024, 256>>>(W, b, pe_coff, t_ptr);

    launch_pdl(k_fused, FUSED_GRID, 256, 0, input, src);

    launch_pdl(k_scale, (N_NODES + 255) / 256, 256, 0);

    launch_pdl(k_agg, n_sm, 1024, AGG_SMEM, src, dst);

    {
        int total16 = N_NODES * (N_HID / 16);          // 1.6M threads
        launch_pdl(k_out, (total16 + 255) / 256, 256, 0, out);
    }
}

// round 16
// speedup vs baseline: 1.3590x; 1.3590x over previous
#include <cuda_runtime.h>
#include <cuda_fp16.h>
#include <math.h>

#define N_NODES 100000
#define N_HID   256
#define N_EDGES 3200000

// bit-reinterpret helpers
static __device__ __forceinline__ unsigned h2_to_u32(__half2 h) {
    union { __half2 h; unsigned u; } c; c.h = h; return c.u;
}
static __device__ __forceinline__ __half2 u32_to_h2(unsigned u) {
    union { unsigned u; __half2 h; } c; c.u = u; return c.h;
}

// ---- scratch in device globals (no allocation allowed) ----
__device__ int    g_out_deg[N_NODES];
__device__ float  g_hun[N_NODES];                       // unscaled dot
__device__ __half g_h1h[N_NODES];                       // scaled h, fp16 gather table
__device__ __align__(8) float2 g_aggcnt[N_NODES];       // {agg_sum, in_deg_count}
__device__ __align__(16) __half g_xh[N_NODES * N_HID];  // x = input + pe, fp16
__device__ float  g_W1[N_HID];                          // W[:,1]
__device__ float  g_pe_s[N_HID];                        // pe_coff * pe(t+1)
__device__ float  g_pe_dot;
__device__ float  g_b1;

// K0: zero scratch + compute PE row, W1, pe_dot, b1.
__global__ void k_init(const float* __restrict__ W,
                       const float* __restrict__ b,
                       const float* __restrict__ pe_coff,
                       const int*   __restrict__ t_ptr) {
    int i = blockIdx.x * blockDim.x + threadIdx.x;
    if (i < N_NODES) {
        g_out_deg[i] = 0;
        g_aggcnt[i]  = make_float2(0.0f, 0.0f);
    }
    if (blockIdx.x == 0) {
        int c = threadIdx.x;               // 256 threads == N_HID
        float w1 = W[c * 2 + 1];
        g_W1[c] = w1;
        int t = *t_ptr;
        float pos  = (float)(t + 1);
        float coff = pe_coff[0];
        int even = c & ~1;
        float div = expf((float)even * (-logf(10000.0f) / (float)N_HID));
        float pe  = (c & 1) ? cosf(pos * div) : sinf(pos * div);
        float pes = coff * pe;
        g_pe_s[c] = pes;
        __shared__ float sred[256];
        sred[c] = pes * w1;
        __syncthreads();
        for (int s = 128; s > 0; s >>= 1) {
            if (c < s) sred[c] += sred[c + s];
            __syncthreads();
        }
        if (c == 0) {
            g_pe_dot = sred[0];
            g_b1 = b[1];
        }
    }
}

// K1 fused: interleaved block roles (1 edge block per 4 node blocks).
#define FUSED_GRID 15625
__global__ void k_fused(const float* __restrict__ input,
                        const int*   __restrict__ src) {
    int b = blockIdx.x;
    if (b % 5 == 0) {
        // ---- edge role: out-degree atomics ----
        int eb = b / 5;
        int i = eb * 256 + threadIdx.x;
        int4 s = make_int4(0, 0, 0, 0);
        bool act = (i < N_EDGES / 4);
        if (act) s = __ldcs(&((const int4*)src)[i]);   // streaming
        cudaGridDependencySynchronize();               // k_init zeroed counters
        if (act) {
            atomicAdd(&g_out_deg[s.x], 1);
            atomicAdd(&g_out_deg[s.y], 1);
            atomicAdd(&g_out_deg[s.z], 1);
            atomicAdd(&g_out_deg[s.w], 1);
        }
    } else {
        // ---- node role: dot(input[r], W1) + write x_h[r] fp16 ----
        int nb = b - (b / 5 + 1);            // 0..12499
        int warp_in_block = threadIdx.x >> 5;
        int lane = threadIdx.x & 31;
        int row = nb * 8 + warp_in_block;
        float4 v0 = make_float4(0, 0, 0, 0), v1 = v0;
        bool act = (row < N_NODES);
        if (act) {
            const float4* rowp = (const float4*)(input + (size_t)row * N_HID);
            v0 = __ldcs(&rowp[2 * lane]);       // streaming: not needed later
            v1 = __ldcs(&rowp[2 * lane + 1]);
        }
        cudaGridDependencySynchronize();               // g_W1 / g_pe_s from k_init
        if (act) {
            const float4* w4 = (const float4*)g_W1;
            const float4* p4 = (const float4*)g_pe_s;
            float4 w0 = w4[2 * lane];
            float4 w1 = w4[2 * lane + 1];
            float acc = v0.x * w0.x + v0.y * w0.y + v0.z * w0.z + v0.w * w0.w
                      + v1.x * w1.x + v1.y * w1.y + v1.z * w1.z + v1.w * w1.w;
#pragma unroll
            for (int o = 16; o > 0; o >>= 1)
                acc += __shfl_xor_sync(0xffffffffu, acc, o);
            if (lane == 0) g_hun[row] = acc;
            float4 p0 = p4[2 * lane];
            float4 p1 = p4[2 * lane + 1];
            uint4 pk;
            pk.x = h2_to_u32(__floats2half2_rn(v0.x + p0.x, v0.y + p0.y));
            pk.y = h2_to_u32(__floats2half2_rn(v0.z + p0.z, v0.w + p0.w));
            pk.z = h2_to_u32(__floats2half2_rn(v1.x + p1.x, v1.y + p1.y));
            pk.w = h2_to_u32(__floats2half2_rn(v1.z + p1.z, v1.w + p1.w));
            ((uint4*)g_xh)[(size_t)row * 32 + lane] = pk;   // default: L2-resident
        }
    }
}

// K2: scale by out-degree norm, store fp16 gather table (tiny)
__global__ void k_scale() {
    int i = blockIdx.x * blockDim.x + threadIdx.x;
    cudaGridDependencySynchronize();
    if (i >= N_NODES) return;
    float od = (float)max(g_out_deg[i], 1);
    g_h1h[i] = __float2half((g_hun[i] + g_pe_dot) * rsqrtf(od));
}

// K3: persistent edge aggregation. fp16 h table in SMEM (LDS gather),
//     one fp32 v2 RED per edge: {h,1} -> {agg,cnt}.
__global__ void __launch_bounds__(1024, 1)
k_agg(const int* __restrict__ src, const int* __restrict__ dst) {
    extern __shared__ __half sh[];   // N_NODES halves = 200000 bytes
    int tid = blockIdx.x * blockDim.x + threadIdx.x;
    int nth = gridDim.x * blockDim.x;
    cudaGridDependencySynchronize();                   // h table ready (k_scale)
    for (int j = threadIdx.x; j < N_NODES / 8; j += blockDim.x)
        ((uint4*)sh)[j] = ((const uint4*)g_h1h)[j];
    __syncthreads();
    const float one = 1.0f;
    const int n4 = N_EDGES / 4;
    for (int i = tid; i < n4; i += nth) {
        int4 s = __ldcs(&((const int4*)src)[i]);
        int4 d = __ldcs(&((const int4*)dst)[i]);
        float h0 = __half2float(sh[s.x]);
        float h1 = __half2float(sh[s.y]);
        float h2 = __half2float(sh[s.z]);
        float h3 = __half2float(sh[s.w]);
#define REDV2(p, h) asm volatile("red.global.add.v2.f32 [%0], {%1, %2};" :: "l"(p), "f"(h), "f"(one) : "memory")
        REDV2(&g_aggcnt[d.x], h0);
        REDV2(&g_aggcnt[d.y], h1);
        REDV2(&g_aggcnt[d.z], h2);
        REDV2(&g_aggcnt[d.w], h3);
#undef REDV2
    }
}

// K4: out[r][c] = x_h[r][c] * gate(r).  16 floats/thread.
//     PROLOGUE loads x_h BEFORE the PDL sync (x_h final since k_fused,
//     two launches back) — overlaps the 51MB read with k_agg's atomic tail.
__global__ void __launch_bounds__(256)
k_out(float* __restrict__ out) {
    int idx = blockIdx.x * blockDim.x + threadIdx.x;   // 0 .. 1.6M-1
    const int total16 = N_NODES * (N_HID / 16);        // 1.6M
    bool act = (idx < total16);
    uint4 pka = make_uint4(0, 0, 0, 0), pkb = pka;
    if (act) {
        pka = __ldg(&((const uint4*)g_xh)[2 * idx]);
        pkb = __ldg(&((const uint4*)g_xh)[2 * idx + 1]);
    }
    cudaGridDependencySynchronize();                   // aggcnt final
    if (!act) return;
    int row = idx >> 4;                                // N_HID/16 == 16
    float2 ac = g_aggcnt[row];
    float z = ac.x * rsqrtf(fmaxf(ac.y, 1.0f)) + g_b1;
    z = fmaxf(z, 0.0f);
    float gate = 1.0f / (1.0f + expf(-z));
    float* p = out + (size_t)idx * 16;
#define GATE8(pk, ptr)                                                         \
    {                                                                          \
        float2 f0 = __half22float2(u32_to_h2((pk).x));                         \
        float2 f1 = __half22float2(u32_to_h2((pk).y));                         \
        float2 f2 = __half22float2(u32_to_h2((pk).z));                         \
        float2 f3 = __half22float2(u32_to_h2((pk).w));                         \
        asm volatile("st.global.cs.v8.f32 [%0], {%1,%2,%3,%4,%5,%6,%7,%8};"    \
                     :: "l"(ptr),                                              \
                        "f"(f0.x * gate), "f"(f0.y * gate),                    \
                        "f"(f1.x * gate), "f"(f1.y * gate),                    \
                        "f"(f2.x * gate), "f"(f2.y * gate),                    \
                        "f"(f3.x * gate), "f"(f3.y * gate) : "memory");        \
    }
    GATE8(pka, p);
    GATE8(pkb, p + 8);
#undef GATE8
}

template <typename K, typename... Args>
static inline void launch_pdl(K kern, int grid, int block, size_t smem, Args... args) {
    cudaLaunchConfig_t cfg = {};
    cfg.gridDim = dim3(grid, 1, 1);
    cfg.blockDim = dim3(block, 1, 1);
    cfg.dynamicSmemBytes = smem;
    cfg.stream = 0;
    cudaLaunchAttribute attr[1];
    attr[0].id = cudaLaunchAttributeProgrammaticStreamSerialization;
    attr[0].val.programmaticStreamSerializationAllowed = 1;
    cfg.attrs = attr;
    cfg.numAttrs = 1;
    cudaLaunchKernelEx(&cfg, kern, args...);
}

extern "C" void kernel_launch(void* const* d_in, const int* in_sizes, int n_in,
                              void* d_out, int out_size) {
    const float* input   = (const float*)d_in[0];
    const float* W       = (const float*)d_in[1];
    const float* b       = (const float*)d_in[2];
    const float* pe_coff = (const float*)d_in[3];
    const int*   src     = (const int*)d_in[4];
    const int*   dst     = (const int*)d_in[5];
    const int*   t_ptr   = (const int*)d_in[6];
    float* out = (float*)d_out;

    const size_t AGG_SMEM = (size_t)N_NODES * sizeof(__half);   // 200000 B
    cudaFuncSetAttribute(k_agg, cudaFuncAttributeMaxDynamicSharedMemorySize,
                         (int)AGG_SMEM);
    int n_sm = 148;
    cudaDeviceGetAttribute(&n_sm, cudaDevAttrMultiProcessorCount, 0);
    if (n_sm <= 0) n_sm = 148;

    k_init<<<1024, 256>>>(W, b, pe_coff, t_ptr);

    launch_pdl(k_fused, FUSED_GRID, 256, 0, input, src);

    launch_pdl(k_scale, (N_NODES + 255) / 256, 256, 0);

    launch_pdl(k_agg, n_sm, 1024, AGG_SMEM, src, dst);

    {
        int total16 = N_NODES * (N_HID / 16);          // 1.6M threads
        launch_pdl(k_out, (total16 + 255) / 256, 256, 0, out);
    }
}

// round 17
// speedup vs baseline: 1.3836x; 1.0181x over previous
#include <cuda_runtime.h>
#include <cuda_fp16.h>
#include <math.h>

#define N_NODES 100000
#define N_HID   256
#define N_EDGES 3200000

// bit-reinterpret helpers
static __device__ __forceinline__ unsigned h2_to_u32(__half2 h) {
    union { __half2 h; unsigned u; } c; c.h = h; return c.u;
}
static __device__ __forceinline__ __half2 u32_to_h2(unsigned u) {
    union { unsigned u; __half2 h; } c; c.u = u; return c.h;
}

// ---- scratch in device globals (no allocation allowed) ----
__device__ int    g_out_deg[N_NODES];
__device__ float  g_hun[N_NODES];                       // unscaled dot
__device__ __half g_h1h[N_NODES];                       // scaled h, fp16 gather table
__device__ __align__(8) float2 g_aggcnt[N_NODES];       // {agg_sum, in_deg_count}
__device__ __align__(16) __half g_xh[N_NODES * N_HID];  // x = input + pe, fp16
__device__ float  g_W1[N_HID];                          // W[:,1]
__device__ float  g_pe_s[N_HID];                        // pe_coff * pe(t+1)
__device__ float  g_pe_dot;
__device__ float  g_b1;
__device__ unsigned g_bar;                              // k_agg grid barrier

// K0: zero scratch + barrier counter + compute PE row, W1, pe_dot, b1.
__global__ void k_init(const float* __restrict__ W,
                       const float* __restrict__ b,
                       const float* __restrict__ pe_coff,
                       const int*   __restrict__ t_ptr) {
    int i = blockIdx.x * blockDim.x + threadIdx.x;
    if (i < N_NODES) {
        g_out_deg[i] = 0;
        g_aggcnt[i]  = make_float2(0.0f, 0.0f);
    }
    if (i == 0) g_bar = 0u;
    if (blockIdx.x == 0) {
        int c = threadIdx.x;               // 256 threads == N_HID
        float w1 = W[c * 2 + 1];
        g_W1[c] = w1;
        int t = *t_ptr;
        float pos  = (float)(t + 1);
        float coff = pe_coff[0];
        int even = c & ~1;
        float div = expf((float)even * (-logf(10000.0f) / (float)N_HID));
        float pe  = (c & 1) ? cosf(pos * div) : sinf(pos * div);
        float pes = coff * pe;
        g_pe_s[c] = pes;
        __shared__ float sred[256];
        sred[c] = pes * w1;
        __syncthreads();
        for (int s = 128; s > 0; s >>= 1) {
            if (c < s) sred[c] += sred[c + s];
            __syncthreads();
        }
        if (c == 0) {
            g_pe_dot = sred[0];
            g_b1 = b[1];
        }
    }
}

// K1 fused: interleaved block roles (1 edge block per 4 node blocks).
#define FUSED_GRID 15625
__global__ void k_fused(const float* __restrict__ input,
                        const int*   __restrict__ src) {
    int b = blockIdx.x;
    if (b % 5 == 0) {
        // ---- edge role: out-degree atomics ----
        int eb = b / 5;
        int i = eb * 256 + threadIdx.x;
        int4 s = make_int4(0, 0, 0, 0);
        bool act = (i < N_EDGES / 4);
        if (act) s = __ldcs(&((const int4*)src)[i]);   // streaming
        cudaGridDependencySynchronize();               // k_init zeroed counters
        if (act) {
            atomicAdd(&g_out_deg[s.x], 1);
            atomicAdd(&g_out_deg[s.y], 1);
            atomicAdd(&g_out_deg[s.z], 1);
            atomicAdd(&g_out_deg[s.w], 1);
        }
    } else {
        // ---- node role: dot(input[r], W1) + write x_h[r] fp16 ----
        int nb = b - (b / 5 + 1);            // 0..12499
        int warp_in_block = threadIdx.x >> 5;
        int lane = threadIdx.x & 31;
        int row = nb * 8 + warp_in_block;
        float4 v0 = make_float4(0, 0, 0, 0), v1 = v0;
        bool act = (row < N_NODES);
        if (act) {
            const float4* rowp = (const float4*)(input + (size_t)row * N_HID);
            v0 = __ldcs(&rowp[2 * lane]);       // streaming: not needed later
            v1 = __ldcs(&rowp[2 * lane + 1]);
        }
        cudaGridDependencySynchronize();               // g_W1 / g_pe_s from k_init
        if (act) {
            const float4* w4 = (const float4*)g_W1;
            const float4* p4 = (const float4*)g_pe_s;
            float4 w0 = w4[2 * lane];
            float4 w1 = w4[2 * lane + 1];
            float acc = v0.x * w0.x + v0.y * w0.y + v0.z * w0.z + v0.w * w0.w
                      + v1.x * w1.x + v1.y * w1.y + v1.z * w1.z + v1.w * w1.w;
#pragma unroll
            for (int o = 16; o > 0; o >>= 1)
                acc += __shfl_xor_sync(0xffffffffu, acc, o);
            if (lane == 0) g_hun[row] = acc;
            float4 p0 = p4[2 * lane];
            float4 p1 = p4[2 * lane + 1];
            uint4 pk;
            pk.x = h2_to_u32(__floats2half2_rn(v0.x + p0.x, v0.y + p0.y));
            pk.y = h2_to_u32(__floats2half2_rn(v0.z + p0.z, v0.w + p0.w));
            pk.z = h2_to_u32(__floats2half2_rn(v1.x + p1.x, v1.y + p1.y));
            pk.w = h2_to_u32(__floats2half2_rn(v1.z + p1.z, v1.w + p1.w));
            ((uint4*)g_xh)[(size_t)row * 32 + lane] = pk;   // default: L2-resident
        }
    }
}

// K3: persistent edge aggregation WITH inlined scale preamble.
//     post-sync: each block scales its node slice into g_h1h, grid barrier,
//     cooperative smem table load, then the RED loop (unchanged).
__global__ void __launch_bounds__(1024, 1)
k_agg(const int* __restrict__ src, const int* __restrict__ dst) {
    extern __shared__ __half sh[];   // N_NODES halves = 200000 bytes
    const int tid = blockIdx.x * blockDim.x + threadIdx.x;
    const int nth = gridDim.x * blockDim.x;
    cudaGridDependencySynchronize();                   // k_fused done (hun, deg)

    // ---- inlined k_scale: this block's slice of the fp16 h table ----
    for (int i = tid; i < N_NODES; i += nth) {
        float od = (float)max(g_out_deg[i], 1);
        g_h1h[i] = __float2half((g_hun[i] + g_pe_dot) * rsqrtf(od));
    }
    // ---- grid barrier (all blocks resident: 1/SM) ----
    __syncthreads();
    if (threadIdx.x == 0) {
        __threadfence();                               // publish h1h slice
        atomicAdd(&g_bar, 1u);
        while (*(volatile unsigned*)&g_bar < gridDim.x) __nanosleep(32);
    }
    __syncthreads();
    __threadfence();                                   // acquire peers' slices

    // ---- cooperative smem table load ----
    for (int j = threadIdx.x; j < N_NODES / 8; j += blockDim.x)
        ((uint4*)sh)[j] = ((const uint4*)g_h1h)[j];
    __syncthreads();

    const float one = 1.0f;
    const int n4 = N_EDGES / 4;
    for (int i = tid; i < n4; i += nth) {
        int4 s = __ldcs(&((const int4*)src)[i]);
        int4 d = __ldcs(&((const int4*)dst)[i]);
        float h0 = __half2float(sh[s.x]);
        float h1 = __half2float(sh[s.y]);
        float h2 = __half2float(sh[s.z]);
        float h3 = __half2float(sh[s.w]);
#define REDV2(p, h) asm volatile("red.global.add.v2.f32 [%0], {%1, %2};" :: "l"(p), "f"(h), "f"(one) : "memory")
        REDV2(&g_aggcnt[d.x], h0);
        REDV2(&g_aggcnt[d.y], h1);
        REDV2(&g_aggcnt[d.z], h2);
        REDV2(&g_aggcnt[d.w], h3);
#undef REDV2
    }
}

// K4: out[r][c] = x_h[r][c] * gate(r).  16 floats/thread.
//     PROLOGUE loads x_h BEFORE the PDL sync (x_h final since k_fused).
__global__ void __launch_bounds__(256)
k_out(float* __restrict__ out) {
    int idx = blockIdx.x * blockDim.x + threadIdx.x;   // 0 .. 1.6M-1
    const int total16 = N_NODES * (N_HID / 16);        // 1.6M
    bool act = (idx < total16);
    uint4 pka = make_uint4(0, 0, 0, 0), pkb = pka;
    if (act) {
        pka = __ldg(&((const uint4*)g_xh)[2 * idx]);
        pkb = __ldg(&((const uint4*)g_xh)[2 * idx + 1]);
    }
    cudaGridDependencySynchronize();                   // aggcnt final
    if (!act) return;
    int row = idx >> 4;                                // N_HID/16 == 16
    float2 ac = g_aggcnt[row];
    float z = ac.x * rsqrtf(fmaxf(ac.y, 1.0f)) + g_b1;
    z = fmaxf(z, 0.0f);
    float gate = 1.0f / (1.0f + expf(-z));
    float* p = out + (size_t)idx * 16;
#define GATE8(pk, ptr)                                                         \
    {                                                                          \
        float2 f0 = __half22float2(u32_to_h2((pk).x));                         \
        float2 f1 = __half22float2(u32_to_h2((pk).y));                         \
        float2 f2 = __half22float2(u32_to_h2((pk).z));                         \
        float2 f3 = __half22float2(u32_to_h2((pk).w));                         \
        asm volatile("st.global.cs.v8.f32 [%0], {%1,%2,%3,%4,%5,%6,%7,%8};"    \
                     :: "l"(ptr),                                              \
                        "f"(f0.x * gate), "f"(f0.y * gate),                    \
                        "f"(f1.x * gate), "f"(f1.y * gate),                    \
                        "f"(f2.x * gate), "f"(f2.y * gate),                    \
                        "f"(f3.x * gate), "f"(f3.y * gate) : "memory");        \
    }
    GATE8(pka, p);
    GATE8(pkb, p + 8);
#undef GATE8
}

template <typename K, typename... Args>
static inline void launch_pdl(K kern, int grid, int block, size_t smem, Args... args) {
    cudaLaunchConfig_t cfg = {};
    cfg.gridDim = dim3(grid, 1, 1);
    cfg.blockDim = dim3(block, 1, 1);
    cfg.dynamicSmemBytes = smem;
    cfg.stream = 0;
    cudaLaunchAttribute attr[1];
    attr[0].id = cudaLaunchAttributeProgrammaticStreamSerialization;
    attr[0].val.programmaticStreamSerializationAllowed = 1;
    cfg.attrs = attr;
    cfg.numAttrs = 1;
    cudaLaunchKernelEx(&cfg, kern, args...);
}

extern "C" void kernel_launch(void* const* d_in, const int* in_sizes, int n_in,
                              void* d_out, int out_size) {
    const float* input   = (const float*)d_in[0];
    const float* W       = (const float*)d_in[1];
    const float* b       = (const float*)d_in[2];
    const float* pe_coff = (const float*)d_in[3];
    const int*   src     = (const int*)d_in[4];
    const int*   dst     = (const int*)d_in[5];
    const int*   t_ptr   = (const int*)d_in[6];
    float* out = (float*)d_out;

    const size_t AGG_SMEM = (size_t)N_NODES * sizeof(__half);   // 200000 B
    cudaFuncSetAttribute(k_agg, cudaFuncAttributeMaxDynamicSharedMemorySize,
                         (int)AGG_SMEM);
    int n_sm = 148;
    cudaDeviceGetAttribute(&n_sm, cudaDevAttrMultiProcessorCount, 0);
    if (n_sm <= 0) n_sm = 148;

    k_init<<<1024, 256>>>(W, b, pe_coff, t_ptr);

    launch_pdl(k_fused, FUSED_GRID, 256, 0, input, src);

    launch_pdl(k_agg, n_sm, 1024, AGG_SMEM, src, dst);

    {
        int total16 = N_NODES * (N_HID / 16);          // 1.6M threads
        launch_pdl(k_out, (total16 + 255) / 256, 256, 0, out);
    }
}